// round 16
// baseline (speedup 1.0000x reference)
#include <cuda_runtime.h>

#define B_ 4096
#define T_ 256
#define C_ 64
#define H_ 16
#define D_ 16
#define S_ 10
#define TO_ 255

#define NCH 4
#define BCH (B_ / NCH)              // 1024 batches per chunk
#define RCH ((long)BCH * T_)        // 262144 rows per chunk

// PLANAR xw: plane j at g_xw[j*B*T + b*T + t]
__device__ float g_xw[(long)H_ * B_ * T_];
__device__ float g_hs[(long)B_ * T_ * H_];   // RNN hidden states, row-major
// PLANAR tr: plane j at g_tr[j*B*T + b*T + (t-1)], t in [1,256)
__device__ float g_tr[(long)10 * B_ * T_];

// ---- fast transcendentals ----
__device__ __forceinline__ float fex2(float x) {
    float r; asm("ex2.approx.f32 %0, %1;" : "=f"(r) : "f"(x)); return r;
}
__device__ __forceinline__ float frcp(float x) {
    float r; asm("rcp.approx.f32 %0, %1;" : "=f"(r) : "f"(x)); return r;
}
__device__ __forceinline__ float fsig(float x) {
    return frcp(1.0f + fex2(-1.4426950408889634f * x));
}
__device__ __forceinline__ float ftanh(float x) {
    return fmaf(2.0f, frcp(1.0f + fex2(-2.8853900817779268f * x)), -1.0f);
}

__global__ void k_warm() {}

// ---------------------------------------------------------------------------
// Kernel 1: fused LayerNorm + x@Wx + b (LN folded). 2 rows/thread, pipelined
// cov loads, planar output. Processes rows [rowBase, rowBase+RCH).
// ---------------------------------------------------------------------------
__global__ void __launch_bounds__(256, 2) k_ln_xw(
    const float* __restrict__ cov,
    const float* __restrict__ gamma,
    const float* __restrict__ beta,
    const float* __restrict__ wx,
    const float* __restrict__ rnn_b,
    long rowBase)
{
    __shared__ float sWg[C_ * H_];
    __shared__ float sS1[H_];
    __shared__ float sS2[H_];

    int tid = threadIdx.x;
    for (int i = tid; i < C_ * H_; i += blockDim.x) {
        int c = i >> 4;
        sWg[i] = gamma[c] * wx[i];
    }
    __syncthreads();
    if (tid < H_) {
        float s1 = 0.f, s2 = 0.f;
        for (int c = 0; c < C_; c++) {
            s1 += sWg[c * H_ + tid];
            s2 += beta[c] * wx[c * H_ + tid];
        }
        sS1[tid] = s1;
        sS2[tid] = s2 + rnn_b[tid];
    }
    __syncthreads();

    const float4* wg4 = reinterpret_cast<const float4*>(sWg);

    const long Q = RCH / 2;
    const long BT = (long)B_ * T_;
    long r = rowBase + (long)blockIdx.x * blockDim.x + tid;

    const float4* cv0 = reinterpret_cast<const float4*>(cov + r * C_);
    const float4* cv1 = reinterpret_cast<const float4*>(cov + (r + Q) * C_);

    float acc0[H_], acc1[H_];
#pragma unroll
    for (int j = 0; j < H_; j++) { acc0[j] = 0.f; acc1[j] = 0.f; }
    float sum0 = 0.f, sq0 = 0.f, sum1 = 0.f, sq1 = 0.f;

    float4 curA = cv0[0], curB = cv1[0];

    for (int c4 = 0; c4 < C_ / 4; c4++) {
        float4 nxtA, nxtB;
        if (c4 + 1 < C_ / 4) {
            nxtA = cv0[c4 + 1];
            nxtB = cv1[c4 + 1];
        } else {
            nxtA = make_float4(0.f, 0.f, 0.f, 0.f);
            nxtB = nxtA;
        }
        float xa[4] = {curA.x, curA.y, curA.z, curA.w};
        float xb[4] = {curB.x, curB.y, curB.z, curB.w};
#pragma unroll
        for (int k = 0; k < 4; k++) {
            int c = c4 * 4 + k;
            float4 w0 = wg4[c * 4 + 0];
            float4 w1 = wg4[c * 4 + 1];
            float4 w2 = wg4[c * 4 + 2];
            float4 w3 = wg4[c * 4 + 3];
            float x0 = xa[k], x1 = xb[k];
            sum0 += x0; sq0 = fmaf(x0, x0, sq0);
            sum1 += x1; sq1 = fmaf(x1, x1, sq1);
            acc0[0]  += x0 * w0.x; acc0[1]  += x0 * w0.y;
            acc0[2]  += x0 * w0.z; acc0[3]  += x0 * w0.w;
            acc0[4]  += x0 * w1.x; acc0[5]  += x0 * w1.y;
            acc0[6]  += x0 * w1.z; acc0[7]  += x0 * w1.w;
            acc0[8]  += x0 * w2.x; acc0[9]  += x0 * w2.y;
            acc0[10] += x0 * w2.z; acc0[11] += x0 * w2.w;
            acc0[12] += x0 * w3.x; acc0[13] += x0 * w3.y;
            acc0[14] += x0 * w3.z; acc0[15] += x0 * w3.w;
            acc1[0]  += x1 * w0.x; acc1[1]  += x1 * w0.y;
            acc1[2]  += x1 * w0.z; acc1[3]  += x1 * w0.w;
            acc1[4]  += x1 * w1.x; acc1[5]  += x1 * w1.y;
            acc1[6]  += x1 * w1.z; acc1[7]  += x1 * w1.w;
            acc1[8]  += x1 * w2.x; acc1[9]  += x1 * w2.y;
            acc1[10] += x1 * w2.z; acc1[11] += x1 * w2.w;
            acc1[12] += x1 * w3.x; acc1[13] += x1 * w3.y;
            acc1[14] += x1 * w3.z; acc1[15] += x1 * w3.w;
        }
        curA = nxtA; curB = nxtB;
    }

    {
        float mu = sum0 * (1.f/64.f);
        float rs = rsqrtf(sq0 * (1.f/64.f) - mu*mu + 1e-3f);
        float rm = rs * mu;
#pragma unroll
        for (int j = 0; j < H_; j++)
            g_xw[j * BT + r] = rs * acc0[j] - rm * sS1[j] + sS2[j];
    }
    {
        float mu = sum1 * (1.f/64.f);
        float rs = rsqrtf(sq1 * (1.f/64.f) - mu*mu + 1e-3f);
        float rm = rs * mu;
#pragma unroll
        for (int j = 0; j < H_; j++)
            g_xw[j * BT + (r + Q)] = rs * acc1[j] - rm * sS1[j] + sS2[j];
    }
}

// ---------------------------------------------------------------------------
// Kernel 2: RNN recurrence. Smem h-broadcast, planar xw streaming.
// Processes batches [bBase, bBase+BCH).
// ---------------------------------------------------------------------------
__global__ void __launch_bounds__(128) k_rnn(const float* __restrict__ wh, int bBase)
{
    __shared__ float sh[2][8][H_];

    int tid = threadIdx.x;
    int q = tid & 15;
    int team = tid >> 4;
    int b = bBase + blockIdx.x * 8 + team;

    float whc[H_];
#pragma unroll
    for (int i = 0; i < H_; i++) whc[i] = wh[i * H_ + q];

    const long BT = (long)B_ * T_;
    const float4* xp = reinterpret_cast<const float4*>(g_xw + (long)q * BT + (long)b * T_);
    float* hsp = g_hs + (long)b * T_ * H_;

    float h = 0.f;
    float4 c0 = xp[0], c1 = xp[1];

    for (int t8 = 0; t8 < T_ / 8; t8++) {
        float4 n0, n1;
        if (t8 + 1 < T_ / 8) {
            n0 = xp[(t8 + 1) * 2];
            n1 = xp[(t8 + 1) * 2 + 1];
        } else {
            n0 = make_float4(0.f, 0.f, 0.f, 0.f);
            n1 = n0;
        }
        float xw8[8] = {c0.x, c0.y, c0.z, c0.w, c1.x, c1.y, c1.z, c1.w};
#pragma unroll
        for (int u = 0; u < 8; u++) {
            int pb = u & 1;
            sh[pb][team][q] = h;
            __syncwarp();
            const float4* hv = reinterpret_cast<const float4*>(sh[pb][team]);
            float4 h0 = hv[0], h1 = hv[1], h2 = hv[2], h3 = hv[3];

            float a0 = xw8[u], a1 = 0.f, a2 = 0.f, a3 = 0.f;
            a0 = fmaf(h0.x, whc[0],  a0);
            a1 = fmaf(h0.y, whc[1],  a1);
            a2 = fmaf(h0.z, whc[2],  a2);
            a3 = fmaf(h0.w, whc[3],  a3);
            a0 = fmaf(h1.x, whc[4],  a0);
            a1 = fmaf(h1.y, whc[5],  a1);
            a2 = fmaf(h1.z, whc[6],  a2);
            a3 = fmaf(h1.w, whc[7],  a3);
            a0 = fmaf(h2.x, whc[8],  a0);
            a1 = fmaf(h2.y, whc[9],  a1);
            a2 = fmaf(h2.z, whc[10], a2);
            a3 = fmaf(h2.w, whc[11], a3);
            a0 = fmaf(h3.x, whc[12], a0);
            a1 = fmaf(h3.y, whc[13], a1);
            a2 = fmaf(h3.z, whc[14], a2);
            a3 = fmaf(h3.w, whc[15], a3);

            h = ftanh((a0 + a1) + (a2 + a3));
            hsp[(t8 * 8 + u) * H_ + q] = h;
        }
        c0 = n0; c1 = n1;
    }
}

// ---------------------------------------------------------------------------
// Kernel 3: batched driver MLP + transforms. Rows [rowBase, rowBase+RCH).
// ---------------------------------------------------------------------------
__global__ void __launch_bounds__(256) k_mlp(
    const float* __restrict__ d1w,
    const float* __restrict__ d1b,
    const float* __restrict__ d2w,
    const float* __restrict__ d2b,
    long rowBase)
{
    __shared__ float sw1[H_ * H_];
    __shared__ float sw2[H_ * 10];
    __shared__ float sb1[H_];
    __shared__ float sb2[10];

    int tid = threadIdx.x;
    if (tid < H_ * H_) sw1[tid] = d1w[tid];
    if (tid < H_ * 10) { int i = tid / 10, j = tid % 10; sw2[tid] = d2w[i * D_ + j]; }
    if (tid < H_) sb1[tid] = d1b[tid];
    if (tid < 10) sb2[tid] = d2b[tid];
    __syncthreads();

    long r = rowBase + (long)blockIdx.x * blockDim.x + tid;
    int t = (int)(r & (T_ - 1));
    if (t == 0) return;

    const float4* hp = reinterpret_cast<const float4*>(g_hs + r * H_);
    float4 h4[4] = {hp[0], hp[1], hp[2], hp[3]};
    const float* hv = reinterpret_cast<const float*>(h4);

    const float4* w14 = reinterpret_cast<const float4*>(sw1);
    float a[H_];
#pragma unroll
    for (int j = 0; j < H_; j++) a[j] = sb1[j];
#pragma unroll
    for (int i = 0; i < H_; i++) {
        float xi = hv[i];
        float4 w0 = w14[i * 4 + 0];
        float4 w1 = w14[i * 4 + 1];
        float4 w2 = w14[i * 4 + 2];
        float4 w3 = w14[i * 4 + 3];
        a[0]  += xi * w0.x; a[1]  += xi * w0.y; a[2]  += xi * w0.z; a[3]  += xi * w0.w;
        a[4]  += xi * w1.x; a[5]  += xi * w1.y; a[6]  += xi * w1.z; a[7]  += xi * w1.w;
        a[8]  += xi * w2.x; a[9]  += xi * w2.y; a[10] += xi * w2.z; a[11] += xi * w2.w;
        a[12] += xi * w3.x; a[13] += xi * w3.y; a[14] += xi * w3.z; a[15] += xi * w3.w;
    }
#pragma unroll
    for (int j = 0; j < H_; j++) a[j] = ftanh(a[j]);

    float d[10];
#pragma unroll
    for (int j = 0; j < 10; j++) d[j] = sb2[j];
#pragma unroll
    for (int i = 0; i < H_; i++) {
        float xi = a[i];
        const float2* w2r = reinterpret_cast<const float2*>(sw2 + i * 10);
#pragma unroll
        for (int j2 = 0; j2 < 5; j2++) {
            float2 w = w2r[j2];
            d[j2 * 2]     += xi * w.x;
            d[j2 * 2 + 1] += xi * w.y;
        }
    }

    const long BT = (long)B_ * T_;
    float* p = g_tr + (r - 1);
    p[0 * BT] = fsig(2.0f * d[0]) * 0.4f - 0.2f;
    p[1 * BT] = fsig(d[1]);
    p[2 * BT] = fsig(d[2]) * 0.5f;
    p[3 * BT] = fsig(d[3]) * 0.1f;
    p[4 * BT] = fsig(d[4]) * 0.2f;
    p[5 * BT] = fsig(d[5]);
    p[6 * BT] = fsig(d[6]);
    p[7 * BT] = fsig(d[7]);
    p[8 * BT] = fsig(d[8]) * 0.35f;
    p[9 * BT] = fsig(d[9]) * 0.1f;
}

// ---------------------------------------------------------------------------
// Kernel 4: cash-budget scan. Batches [bBase, bBase+BCH).
// ---------------------------------------------------------------------------
#define SKW(i) ((i) + ((i) >> 5))
#define STG_W 2632
#define ISG_W 1844

__global__ void __launch_bounds__(128) k_cash(
    const float* __restrict__ states_seq,
    float* __restrict__ out,
    int bBase)
{
    __shared__ float sbuf[4 * STG_W];

    const unsigned FULL = 0xffffffffu;
    int lane = threadIdx.x & 31;
    int w = threadIdx.x >> 5;
    int bg = blockIdx.x * 4 + w;          // block-group index within chunk
    int b = bBase + bg;
    int o0 = lane * 8;
    int n = (lane == 31) ? 7 : 8;

    const float* s0 = states_seq + (long)b * T_ * S_;
    float s0rev = s0[0], s0cash = s0[1], s0ar = s0[2], s0inv = s0[3], s0ppe = s0[4],
          s0ap  = s0[5], debt = s0[6], eqty = s0[7], s0re = s0[8], oth = s0[9];

    const long BT = (long)B_ * T_;
    float tr[8][10];
    {
        const float* base = g_tr + (long)b * T_ + o0;
#pragma unroll
        for (int j = 0; j < 10; j++) {
            float4 v0 = *reinterpret_cast<const float4*>(base + j * BT);
            float4 v1 = *reinterpret_cast<const float4*>(base + j * BT + 4);
            tr[0][j] = v0.x; tr[1][j] = v0.y; tr[2][j] = v0.z; tr[3][j] = v0.w;
            tr[4][j] = v1.x; tr[5][j] = v1.y; tr[6][j] = v1.z; tr[7][j] = v1.w;
        }
    }

    // ---- phase 1: revenue product scan ----
    float Pg = 1.f;
#pragma unroll
    for (int k = 0; k < 8; k++) if (k < n) Pg *= (1.f + tr[k][0]);
    float p = Pg;
#pragma unroll
    for (int dd = 1; dd < 32; dd <<= 1) {
        float v = __shfl_up_sync(FULL, p, dd);
        if (lane >= dd) p *= v;
    }
    float pe = __shfl_up_sync(FULL, p, 1);
    if (lane == 0) pe = 1.f;
    float revS = s0rev * pe;

    // ---- phase 2: rev stepwise + ppe affine scan ----
    float rev[8];
    float A = 1.f, Bc = 0.f, rprev = revS;
#pragma unroll
    for (int k = 0; k < 8; k++) {
        if (k < n) {
            rprev *= (1.f + tr[k][0]);
            rev[k] = rprev;
            float om = 1.f - tr[k][3];
            A = A * om;
            Bc = fmaf(Bc, om, tr[k][4] * rprev);
        } else rev[k] = rprev;
    }
    float a_ = A, b_ = Bc;
#pragma unroll
    for (int dd = 1; dd < 32; dd <<= 1) {
        float av = __shfl_up_sync(FULL, a_, dd);
        float bv = __shfl_up_sync(FULL, b_, dd);
        if (lane >= dd) { b_ = fmaf(bv, a_, b_); a_ = av * a_; }
    }
    float aex = __shfl_up_sync(FULL, a_, 1);
    float bex = __shfl_up_sync(FULL, b_, 1);
    if (lane == 0) { aex = 1.f; bex = 0.f; }
    float ppeS = fmaf(aex, s0ppe, bex);

    // ---- chunk-boundary lagged ar/inv/ap ----
    float pr1 = __shfl_up_sync(FULL, tr[7][1], 1);
    float pr5 = __shfl_up_sync(FULL, tr[7][5], 1);
    float pr6 = __shfl_up_sync(FULL, tr[7][6], 1);
    float pr7 = __shfl_up_sync(FULL, tr[7][7], 1);
    float arP, invP, apP;
    if (lane == 0) { arP = s0ar; invP = s0inv; apP = s0ap; }
    else {
        float cogsP = pr1 * revS;
        arP = pr5 * revS; invP = pr6 * cogsP; apP = pr7 * cogsP;
    }

    // ---- phase 3: chunk sums of cash & re increments ----
    float Cs = 0.f, Rs = 0.f;
    {
        float ppeP = ppeS, arp = arP, invp = invP, app = apP;
#pragma unroll
        for (int k = 0; k < 8; k++) {
            if (k < n) {
                float nrev = rev[k];
                float cogs = tr[k][1] * nrev;
                float opex = tr[k][2] * nrev;
                float dep  = tr[k][3] * ppeP;
                float intr = tr[k][9] * debt;
                float ebt  = nrev - cogs - opex - dep - intr;
                float tax  = tr[k][8] * fmaxf(ebt, 0.f);
                float ni   = ebt - tax;
                float arn  = tr[k][5] * nrev;
                float invn = tr[k][6] * cogs;
                float apn  = tr[k][7] * cogs;
                float capex = tr[k][4] * nrev;
                float cinc = ni + dep - capex - (arn - arp) - (invn - invp) + (apn - app);
                Cs += cinc; Rs += ni;
                ppeP = ppeP + capex - dep;
                arp = arn; invp = invn; app = apn;
            }
        }
    }
    float c = Cs;
#pragma unroll
    for (int dd = 1; dd < 32; dd <<= 1) {
        float v = __shfl_up_sync(FULL, c, dd);
        if (lane >= dd) c += v;
    }
    float ce = __shfl_up_sync(FULL, c, 1);
    if (lane == 0) ce = 0.f;
    float cashS = s0cash + ce;

    float rr = Rs;
#pragma unroll
    for (int dd = 1; dd < 32; dd <<= 1) {
        float v = __shfl_up_sync(FULL, rr, dd);
        if (lane >= dd) rr += v;
    }
    float re_e = __shfl_up_sync(FULL, rr, 1);
    if (lane == 0) re_e = 0.f;
    float reS = s0re + re_e;

    // ---- phase 4a: states walk -> skewed smem ----
    {
        float* sw = sbuf + w * STG_W;
        float cash = cashS, re = reS;
        float ppeP = ppeS, arp = arP, invp = invP, app = apP;
#pragma unroll
        for (int k = 0; k < 8; k++) {
            if (k < n) {
                float nrev = rev[k];
                float cogs = tr[k][1] * nrev;
                float opex = tr[k][2] * nrev;
                float dep  = tr[k][3] * ppeP;
                float intr = tr[k][9] * debt;
                float ebt  = nrev - cogs - opex - dep - intr;
                float tax  = tr[k][8] * fmaxf(ebt, 0.f);
                float ni   = ebt - tax;
                float arn  = tr[k][5] * nrev;
                float invn = tr[k][6] * cogs;
                float apn  = tr[k][7] * cogs;
                float capex = tr[k][4] * nrev;
                float ppen = ppeP + capex - dep;
                float cinc = ni + dep - capex - (arn - arp) - (invn - invp) + (apn - app);
                cash += cinc; re += ni;

                int idx = (o0 + k) * S_;
                sw[SKW(idx + 0)] = nrev;  sw[SKW(idx + 1)] = cash;
                sw[SKW(idx + 2)] = arn;   sw[SKW(idx + 3)] = invn;
                sw[SKW(idx + 4)] = ppen;  sw[SKW(idx + 5)] = apn;
                sw[SKW(idx + 6)] = debt;  sw[SKW(idx + 7)] = eqty;
                sw[SKW(idx + 8)] = re;    sw[SKW(idx + 9)] = oth;

                ppeP = ppen; arp = arn; invp = invn; app = apn;
            }
        }
    }
    __syncthreads();

    {
        int tid = threadIdx.x;
#pragma unroll
        for (int w2 = 0; w2 < 4; w2++) {
            const float* s = sbuf + w2 * STG_W;
            float* g = out + (long)(bBase + blockIdx.x * 4 + w2) * TO_ * S_;
            for (int i = tid; i < TO_ * S_; i += 128)
                g[i] = s[SKW(i)];
        }
    }
    __syncthreads();

    // ---- phase 4b: is walk -> skewed smem (reuse buffer) ----
    {
        float* sw = sbuf + w * ISG_W;
        float ppeP = ppeS, arp = arP, invp = invP, app = apP;
#pragma unroll
        for (int k = 0; k < 8; k++) {
            if (k < n) {
                float nrev = rev[k];
                float cogs = tr[k][1] * nrev;
                float opex = tr[k][2] * nrev;
                float dep  = tr[k][3] * ppeP;
                float intr = tr[k][9] * debt;
                float ebt  = nrev - cogs - opex - dep - intr;
                float tax  = tr[k][8] * fmaxf(ebt, 0.f);
                float ni   = ebt - tax;
                float capex = tr[k][4] * nrev;

                int idx = (o0 + k) * 7;
                sw[SKW(idx + 0)] = nrev;  sw[SKW(idx + 1)] = cogs;
                sw[SKW(idx + 2)] = opex;  sw[SKW(idx + 3)] = dep;
                sw[SKW(idx + 4)] = intr;  sw[SKW(idx + 5)] = tax;
                sw[SKW(idx + 6)] = ni;

                ppeP = ppeP + capex - dep;
                arp = tr[k][5] * nrev; invp = tr[k][6] * cogs; app = tr[k][7] * cogs;
            }
        }
    }
    __syncthreads();

    {
        int tid = threadIdx.x;
        float* ob = out + (long)B_ * TO_ * S_;
#pragma unroll
        for (int w2 = 0; w2 < 4; w2++) {
            const float* s = sbuf + w2 * ISG_W;
            float* g = ob + (long)(bBase + blockIdx.x * 4 + w2) * TO_ * 7;
            for (int i = tid; i < TO_ * 7; i += 128)
                g[i] = s[SKW(i)];
        }
    }
}

// ---------------------------------------------------------------------------
// Pipeline resources: created & warmed at static init (before harness mem
// checkpoints). No device-buffer allocation APIs used. Serial fallback if
// creation fails.
// ---------------------------------------------------------------------------
struct PipeRes {
    cudaStream_t sA = nullptr, sB = nullptr;
    cudaEvent_t eF = nullptr, eK0 = nullptr, eK1 = nullptr, eK2 = nullptr,
                eJa = nullptr, eJb = nullptr;
    bool ok = false;
    PipeRes() {
        bool good = true;
        good &= cudaStreamCreateWithFlags(&sA, cudaStreamNonBlocking) == cudaSuccess;
        good &= cudaStreamCreateWithFlags(&sB, cudaStreamNonBlocking) == cudaSuccess;
        good &= cudaEventCreateWithFlags(&eF,  cudaEventDisableTiming) == cudaSuccess;
        good &= cudaEventCreateWithFlags(&eK0, cudaEventDisableTiming) == cudaSuccess;
        good &= cudaEventCreateWithFlags(&eK1, cudaEventDisableTiming) == cudaSuccess;
        good &= cudaEventCreateWithFlags(&eK2, cudaEventDisableTiming) == cudaSuccess;
        good &= cudaEventCreateWithFlags(&eJa, cudaEventDisableTiming) == cudaSuccess;
        good &= cudaEventCreateWithFlags(&eJb, cudaEventDisableTiming) == cudaSuccess;
        if (good) {
            // warm streams + module so no lazy allocation during timed runs
            k_warm<<<1, 32, 0, sA>>>();
            k_warm<<<1, 32, 0, sB>>>();
            good &= cudaDeviceSynchronize() == cudaSuccess;
        }
        ok = good;
    }
};
static PipeRes g_pipe;

static inline void launch_chunk(int c, cudaStream_t st,
    const float* cov, const float* gamma, const float* beta, const float* wx,
    const float* rnn_b, const float* wh, const float* d1w, const float* d1b,
    const float* d2w, const float* d2b, const float* states, float* out,
    bool do_k1)
{
    long rowBase = (long)c * RCH;
    int bBase = c * BCH;
    if (do_k1)
        k_ln_xw<<<(int)(RCH / 2 / 256), 256, 0, st>>>(cov, gamma, beta, wx, rnn_b, rowBase);
    k_rnn<<<BCH / 8, 128, 0, st>>>(wh, bBase);
    k_mlp<<<(int)(RCH / 256), 256, 0, st>>>(d1w, d1b, d2w, d2b, rowBase);
    k_cash<<<BCH / 4, 128, 0, st>>>(states, out, bBase);
}

extern "C" void kernel_launch(void* const* d_in, const int* in_sizes, int n_in,
                              void* d_out, int out_size)
{
    const float* states = (const float*)d_in[0];
    const float* cov    = (const float*)d_in[1];
    const float* gamma  = (const float*)d_in[2];
    const float* beta   = (const float*)d_in[3];
    const float* wx     = (const float*)d_in[4];
    const float* wh     = (const float*)d_in[5];
    const float* rnn_b  = (const float*)d_in[6];
    const float* d1w    = (const float*)d_in[7];
    const float* d1b    = (const float*)d_in[8];
    const float* d2w    = (const float*)d_in[9];
    const float* d2b    = (const float*)d_in[10];
    float* out = (float*)d_out;

    if (g_pipe.ok) {
        cudaStream_t sA = g_pipe.sA, sB = g_pipe.sB;
        // fork both streams from the captured (legacy) stream
        cudaEventRecord(g_pipe.eF, 0);
        cudaStreamWaitEvent(sA, g_pipe.eF, 0);
        cudaStreamWaitEvent(sB, g_pipe.eF, 0);

        // chunk 0 on sA
        k_ln_xw<<<(int)(RCH / 2 / 256), 256, 0, sA>>>(cov, gamma, beta, wx, rnn_b, 0L);
        cudaEventRecord(g_pipe.eK0, sA);
        k_rnn<<<BCH / 8, 128, 0, sA>>>(wh, 0);
        k_mlp<<<(int)(RCH / 256), 256, 0, sA>>>(d1w, d1b, d2w, d2b, 0L);
        k_cash<<<BCH / 4, 128, 0, sA>>>(states, out, 0);

        // chunk 1 on sB (k1 chained after chunk0's k1)
        cudaStreamWaitEvent(sB, g_pipe.eK0, 0);
        k_ln_xw<<<(int)(RCH / 2 / 256), 256, 0, sB>>>(cov, gamma, beta, wx, rnn_b, 1L * RCH);
        cudaEventRecord(g_pipe.eK1, sB);
        k_rnn<<<BCH / 8, 128, 0, sB>>>(wh, 1 * BCH);
        k_mlp<<<(int)(RCH / 256), 256, 0, sB>>>(d1w, d1b, d2w, d2b, 1L * RCH);
        k_cash<<<BCH / 4, 128, 0, sB>>>(states, out, 1 * BCH);

        // chunk 2 on sA
        cudaStreamWaitEvent(sA, g_pipe.eK1, 0);
        k_ln_xw<<<(int)(RCH / 2 / 256), 256, 0, sA>>>(cov, gamma, beta, wx, rnn_b, 2L * RCH);
        cudaEventRecord(g_pipe.eK2, sA);
        k_rnn<<<BCH / 8, 128, 0, sA>>>(wh, 2 * BCH);
        k_mlp<<<(int)(RCH / 256), 256, 0, sA>>>(d1w, d1b, d2w, d2b, 2L * RCH);
        k_cash<<<BCH / 4, 128, 0, sA>>>(states, out, 2 * BCH);

        // chunk 3 on sB
        cudaStreamWaitEvent(sB, g_pipe.eK2, 0);
        k_ln_xw<<<(int)(RCH / 2 / 256), 256, 0, sB>>>(cov, gamma, beta, wx, rnn_b, 3L * RCH);
        k_rnn<<<BCH / 8, 128, 0, sB>>>(wh, 3 * BCH);
        k_mlp<<<(int)(RCH / 256), 256, 0, sB>>>(d1w, d1b, d2w, d2b, 3L * RCH);
        k_cash<<<BCH / 4, 128, 0, sB>>>(states, out, 3 * BCH);

        // join both streams back into the captured stream
        cudaEventRecord(g_pipe.eJa, sA);
        cudaEventRecord(g_pipe.eJb, sB);
        cudaStreamWaitEvent(0, g_pipe.eJa, 0);
        cudaStreamWaitEvent(0, g_pipe.eJb, 0);
    } else {
        // serial fallback (identical numerics)
        for (int c = 0; c < NCH; c++)
            launch_chunk(c, 0, cov, gamma, beta, wx, rnn_b, wh,
                         d1w, d1b, d2w, d2b, states, out, true);
    }
}

// round 17
// speedup vs baseline: 1.1587x; 1.1587x over previous
#include <cuda_runtime.h>

#define B_ 4096
#define T_ 256
#define C_ 64
#define H_ 16
#define D_ 16
#define S_ 10
#define TO_ 255

// PLANAR xw: plane j at g_xw[j*B*T + b*T + t]
__device__ float g_xw[(long)H_ * B_ * T_];
__device__ float g_hs[(long)B_ * T_ * H_];   // RNN hidden states, row-major
// PLANAR tr: plane j at g_tr[j*B*T + b*T + (t-1)], t in [1,256)
__device__ float g_tr[(long)10 * B_ * T_];

// ---- fast transcendentals ----
__device__ __forceinline__ float fex2(float x) {
    float r; asm("ex2.approx.f32 %0, %1;" : "=f"(r) : "f"(x)); return r;
}
__device__ __forceinline__ float frcp(float x) {
    float r; asm("rcp.approx.f32 %0, %1;" : "=f"(r) : "f"(x)); return r;
}
__device__ __forceinline__ float fsig(float x) {
    return frcp(1.0f + fex2(-1.4426950408889634f * x));
}
__device__ __forceinline__ float ftanh(float x) {
    return fmaf(2.0f, frcp(1.0f + fex2(-2.8853900817779268f * x)), -1.0f);
}

// ---------------------------------------------------------------------------
// Kernel 1: fused LayerNorm + x@Wx + b (LN folded). 2 rows per thread,
// software pipeline with PREFETCH DISTANCE 2 (6 float4 in flight/thread)
// to cover the DRAM stall fraction; ~110 regs keeps 2 blocks/SM.
// ---------------------------------------------------------------------------
__global__ void __launch_bounds__(256, 2) k_ln_xw(
    const float* __restrict__ cov,
    const float* __restrict__ gamma,
    const float* __restrict__ beta,
    const float* __restrict__ wx,
    const float* __restrict__ rnn_b)
{
    __shared__ float sWg[C_ * H_];
    __shared__ float sS1[H_];
    __shared__ float sS2[H_];

    int tid = threadIdx.x;
    for (int i = tid; i < C_ * H_; i += blockDim.x) {
        int c = i >> 4;
        sWg[i] = gamma[c] * wx[i];
    }
    __syncthreads();
    if (tid < H_) {
        float s1 = 0.f, s2 = 0.f;
        for (int c = 0; c < C_; c++) {
            s1 += sWg[c * H_ + tid];
            s2 += beta[c] * wx[c * H_ + tid];
        }
        sS1[tid] = s1;
        sS2[tid] = s2 + rnn_b[tid];
    }
    __syncthreads();

    const float4* wg4 = reinterpret_cast<const float4*>(sWg);

    const long Q = (long)B_ * T_ / 2;
    const long BT = (long)B_ * T_;
    long r = (long)blockIdx.x * blockDim.x + tid;

    const float4* cv0 = reinterpret_cast<const float4*>(cov + r * C_);
    const float4* cv1 = reinterpret_cast<const float4*>(cov + (r + Q) * C_);

    float acc0[H_], acc1[H_];
#pragma unroll
    for (int j = 0; j < H_; j++) { acc0[j] = 0.f; acc1[j] = 0.f; }
    float sum0 = 0.f, sq0 = 0.f, sum1 = 0.f, sq1 = 0.f;

    // software pipeline, prefetch distance 2
    float4 cA = cv0[0], cB = cv1[0];
    float4 nA = cv0[1], nB = cv1[1];

    for (int c4 = 0; c4 < C_ / 4; c4++) {
        float4 mA, mB;
        if (c4 + 2 < C_ / 4) {
            mA = cv0[c4 + 2];
            mB = cv1[c4 + 2];
        } else {
            mA = make_float4(0.f, 0.f, 0.f, 0.f);
            mB = mA;
        }
        float xa[4] = {cA.x, cA.y, cA.z, cA.w};
        float xb[4] = {cB.x, cB.y, cB.z, cB.w};
#pragma unroll
        for (int k = 0; k < 4; k++) {
            int c = c4 * 4 + k;
            float4 w0 = wg4[c * 4 + 0];
            float4 w1 = wg4[c * 4 + 1];
            float4 w2 = wg4[c * 4 + 2];
            float4 w3 = wg4[c * 4 + 3];
            float x0 = xa[k], x1 = xb[k];
            sum0 += x0; sq0 = fmaf(x0, x0, sq0);
            sum1 += x1; sq1 = fmaf(x1, x1, sq1);
            acc0[0]  += x0 * w0.x; acc0[1]  += x0 * w0.y;
            acc0[2]  += x0 * w0.z; acc0[3]  += x0 * w0.w;
            acc0[4]  += x0 * w1.x; acc0[5]  += x0 * w1.y;
            acc0[6]  += x0 * w1.z; acc0[7]  += x0 * w1.w;
            acc0[8]  += x0 * w2.x; acc0[9]  += x0 * w2.y;
            acc0[10] += x0 * w2.z; acc0[11] += x0 * w2.w;
            acc0[12] += x0 * w3.x; acc0[13] += x0 * w3.y;
            acc0[14] += x0 * w3.z; acc0[15] += x0 * w3.w;
            acc1[0]  += x1 * w0.x; acc1[1]  += x1 * w0.y;
            acc1[2]  += x1 * w0.z; acc1[3]  += x1 * w0.w;
            acc1[4]  += x1 * w1.x; acc1[5]  += x1 * w1.y;
            acc1[6]  += x1 * w1.z; acc1[7]  += x1 * w1.w;
            acc1[8]  += x1 * w2.x; acc1[9]  += x1 * w2.y;
            acc1[10] += x1 * w2.z; acc1[11] += x1 * w2.w;
            acc1[12] += x1 * w3.x; acc1[13] += x1 * w3.y;
            acc1[14] += x1 * w3.z; acc1[15] += x1 * w3.w;
        }
        cA = nA; cB = nB;
        nA = mA; nB = mB;
    }

    {
        float mu = sum0 * (1.f/64.f);
        float rs = rsqrtf(sq0 * (1.f/64.f) - mu*mu + 1e-3f);
        float rm = rs * mu;
#pragma unroll
        for (int j = 0; j < H_; j++)
            g_xw[j * BT + r] = rs * acc0[j] - rm * sS1[j] + sS2[j];
    }
    {
        float mu = sum1 * (1.f/64.f);
        float rs = rsqrtf(sq1 * (1.f/64.f) - mu*mu + 1e-3f);
        float rm = rs * mu;
#pragma unroll
        for (int j = 0; j < H_; j++)
            g_xw[j * BT + (r + Q)] = rs * acc1[j] - rm * sS1[j] + sS2[j];
    }
}

// ---------------------------------------------------------------------------
// Kernel 2: RNN recurrence (R13 version). 16-lane team per batch.
// h broadcast via double-buffered SMEM; xw streamed planar 8 steps ahead.
// ---------------------------------------------------------------------------
__global__ void __launch_bounds__(128) k_rnn(const float* __restrict__ wh)
{
    __shared__ float sh[2][8][H_];

    int tid = threadIdx.x;
    int q = tid & 15;
    int team = tid >> 4;
    int b = blockIdx.x * 8 + team;

    float whc[H_];
#pragma unroll
    for (int i = 0; i < H_; i++) whc[i] = wh[i * H_ + q];

    const long BT = (long)B_ * T_;
    const float4* xp = reinterpret_cast<const float4*>(g_xw + (long)q * BT + (long)b * T_);
    float* hsp = g_hs + (long)b * T_ * H_;

    float h = 0.f;
    float4 c0 = xp[0], c1 = xp[1];

    for (int t8 = 0; t8 < T_ / 8; t8++) {
        float4 n0, n1;
        if (t8 + 1 < T_ / 8) {
            n0 = xp[(t8 + 1) * 2];
            n1 = xp[(t8 + 1) * 2 + 1];
        } else {
            n0 = make_float4(0.f, 0.f, 0.f, 0.f);
            n1 = n0;
        }
        float xw8[8] = {c0.x, c0.y, c0.z, c0.w, c1.x, c1.y, c1.z, c1.w};
#pragma unroll
        for (int u = 0; u < 8; u++) {
            int pb = u & 1;
            sh[pb][team][q] = h;
            __syncwarp();
            const float4* hv = reinterpret_cast<const float4*>(sh[pb][team]);
            float4 h0 = hv[0], h1 = hv[1], h2 = hv[2], h3 = hv[3];

            float a0 = xw8[u], a1 = 0.f, a2 = 0.f, a3 = 0.f;
            a0 = fmaf(h0.x, whc[0],  a0);
            a1 = fmaf(h0.y, whc[1],  a1);
            a2 = fmaf(h0.z, whc[2],  a2);
            a3 = fmaf(h0.w, whc[3],  a3);
            a0 = fmaf(h1.x, whc[4],  a0);
            a1 = fmaf(h1.y, whc[5],  a1);
            a2 = fmaf(h1.z, whc[6],  a2);
            a3 = fmaf(h1.w, whc[7],  a3);
            a0 = fmaf(h2.x, whc[8],  a0);
            a1 = fmaf(h2.y, whc[9],  a1);
            a2 = fmaf(h2.z, whc[10], a2);
            a3 = fmaf(h2.w, whc[11], a3);
            a0 = fmaf(h3.x, whc[12], a0);
            a1 = fmaf(h3.y, whc[13], a1);
            a2 = fmaf(h3.z, whc[14], a2);
            a3 = fmaf(h3.w, whc[15], a3);

            h = ftanh((a0 + a1) + (a2 + a3));
            hsp[(t8 * 8 + u) * H_ + q] = h;
        }
        c0 = n0; c1 = n1;
    }
}

// ---------------------------------------------------------------------------
// Kernel 3: batched driver MLP + transforms (R13 version). Planar output.
// ---------------------------------------------------------------------------
__global__ void __launch_bounds__(256) k_mlp(
    const float* __restrict__ d1w,
    const float* __restrict__ d1b,
    const float* __restrict__ d2w,
    const float* __restrict__ d2b)
{
    __shared__ float sw1[H_ * H_];
    __shared__ float sw2[H_ * 10];
    __shared__ float sb1[H_];
    __shared__ float sb2[10];

    int tid = threadIdx.x;
    if (tid < H_ * H_) sw1[tid] = d1w[tid];
    if (tid < H_ * 10) { int i = tid / 10, j = tid % 10; sw2[tid] = d2w[i * D_ + j]; }
    if (tid < H_) sb1[tid] = d1b[tid];
    if (tid < 10) sb2[tid] = d2b[tid];
    __syncthreads();

    long r = (long)blockIdx.x * blockDim.x + tid;
    int t = (int)(r & (T_ - 1));
    if (t == 0) return;   // drivers for t=0 unused

    const float4* hp = reinterpret_cast<const float4*>(g_hs + r * H_);
    float4 h4[4] = {hp[0], hp[1], hp[2], hp[3]};
    const float* hv = reinterpret_cast<const float*>(h4);

    const float4* w14 = reinterpret_cast<const float4*>(sw1);
    float a[H_];
#pragma unroll
    for (int j = 0; j < H_; j++) a[j] = sb1[j];
#pragma unroll
    for (int i = 0; i < H_; i++) {
        float xi = hv[i];
        float4 w0 = w14[i * 4 + 0];
        float4 w1 = w14[i * 4 + 1];
        float4 w2 = w14[i * 4 + 2];
        float4 w3 = w14[i * 4 + 3];
        a[0]  += xi * w0.x; a[1]  += xi * w0.y; a[2]  += xi * w0.z; a[3]  += xi * w0.w;
        a[4]  += xi * w1.x; a[5]  += xi * w1.y; a[6]  += xi * w1.z; a[7]  += xi * w1.w;
        a[8]  += xi * w2.x; a[9]  += xi * w2.y; a[10] += xi * w2.z; a[11] += xi * w2.w;
        a[12] += xi * w3.x; a[13] += xi * w3.y; a[14] += xi * w3.z; a[15] += xi * w3.w;
    }
#pragma unroll
    for (int j = 0; j < H_; j++) a[j] = ftanh(a[j]);

    float d[10];
#pragma unroll
    for (int j = 0; j < 10; j++) d[j] = sb2[j];
#pragma unroll
    for (int i = 0; i < H_; i++) {
        float xi = a[i];
        const float2* w2r = reinterpret_cast<const float2*>(sw2 + i * 10);
#pragma unroll
        for (int j2 = 0; j2 < 5; j2++) {
            float2 w = w2r[j2];
            d[j2 * 2]     += xi * w.x;
            d[j2 * 2 + 1] += xi * w.y;
        }
    }

    const long BT = (long)B_ * T_;
    float* p = g_tr + (r - 1);     // stored at index t-1 within batch row
    p[0 * BT] = fsig(2.0f * d[0]) * 0.4f - 0.2f;   // tanh(d0)*0.2
    p[1 * BT] = fsig(d[1]);
    p[2 * BT] = fsig(d[2]) * 0.5f;
    p[3 * BT] = fsig(d[3]) * 0.1f;
    p[4 * BT] = fsig(d[4]) * 0.2f;
    p[5 * BT] = fsig(d[5]);
    p[6 * BT] = fsig(d[6]);
    p[7 * BT] = fsig(d[7]);
    p[8 * BT] = fsig(d[8]) * 0.35f;
    p[9 * BT] = fsig(d[9]) * 0.1f;
}

// ---------------------------------------------------------------------------
// Kernel 4: cash-budget scan (R13 version). T-parallel, one warp per batch.
// ---------------------------------------------------------------------------
#define SKW(i) ((i) + ((i) >> 5))
#define STG_W 2632
#define ISG_W 1844

__global__ void __launch_bounds__(128) k_cash(
    const float* __restrict__ states_seq,
    float* __restrict__ out)
{
    __shared__ float sbuf[4 * STG_W];   // 42 KB, reused for both passes

    const unsigned FULL = 0xffffffffu;
    int lane = threadIdx.x & 31;
    int w = threadIdx.x >> 5;
    int b = blockIdx.x * 4 + w;
    int o0 = lane * 8;
    int n = (lane == 31) ? 7 : 8;

    const float* s0 = states_seq + (long)b * T_ * S_;
    float s0rev = s0[0], s0cash = s0[1], s0ar = s0[2], s0inv = s0[3], s0ppe = s0[4],
          s0ap  = s0[5], debt = s0[6], eqty = s0[7], s0re = s0[8], oth = s0[9];

    const long BT = (long)B_ * T_;
    float tr[8][10];
    {
        const float* base = g_tr + (long)b * T_ + o0;
#pragma unroll
        for (int j = 0; j < 10; j++) {
            float4 v0 = *reinterpret_cast<const float4*>(base + j * BT);
            float4 v1 = *reinterpret_cast<const float4*>(base + j * BT + 4);
            tr[0][j] = v0.x; tr[1][j] = v0.y; tr[2][j] = v0.z; tr[3][j] = v0.w;
            tr[4][j] = v1.x; tr[5][j] = v1.y; tr[6][j] = v1.z; tr[7][j] = v1.w;
        }
    }

    // ---- phase 1: revenue product scan ----
    float Pg = 1.f;
#pragma unroll
    for (int k = 0; k < 8; k++) if (k < n) Pg *= (1.f + tr[k][0]);
    float p = Pg;
#pragma unroll
    for (int dd = 1; dd < 32; dd <<= 1) {
        float v = __shfl_up_sync(FULL, p, dd);
        if (lane >= dd) p *= v;
    }
    float pe = __shfl_up_sync(FULL, p, 1);
    if (lane == 0) pe = 1.f;
    float revS = s0rev * pe;

    // ---- phase 2: rev stepwise + ppe affine scan ----
    float rev[8];
    float A = 1.f, Bc = 0.f, rprev = revS;
#pragma unroll
    for (int k = 0; k < 8; k++) {
        if (k < n) {
            rprev *= (1.f + tr[k][0]);
            rev[k] = rprev;
            float om = 1.f - tr[k][3];
            A = A * om;
            Bc = fmaf(Bc, om, tr[k][4] * rprev);
        } else rev[k] = rprev;
    }
    float a_ = A, b_ = Bc;
#pragma unroll
    for (int dd = 1; dd < 32; dd <<= 1) {
        float av = __shfl_up_sync(FULL, a_, dd);
        float bv = __shfl_up_sync(FULL, b_, dd);
        if (lane >= dd) { b_ = fmaf(bv, a_, b_); a_ = av * a_; }
    }
    float aex = __shfl_up_sync(FULL, a_, 1);
    float bex = __shfl_up_sync(FULL, b_, 1);
    if (lane == 0) { aex = 1.f; bex = 0.f; }
    float ppeS = fmaf(aex, s0ppe, bex);

    // ---- chunk-boundary lagged ar/inv/ap ----
    float pr1 = __shfl_up_sync(FULL, tr[7][1], 1);
    float pr5 = __shfl_up_sync(FULL, tr[7][5], 1);
    float pr6 = __shfl_up_sync(FULL, tr[7][6], 1);
    float pr7 = __shfl_up_sync(FULL, tr[7][7], 1);
    float arP, invP, apP;
    if (lane == 0) { arP = s0ar; invP = s0inv; apP = s0ap; }
    else {
        float cogsP = pr1 * revS;
        arP = pr5 * revS; invP = pr6 * cogsP; apP = pr7 * cogsP;
    }

    // ---- phase 3: chunk sums of cash & re increments ----
    float Cs = 0.f, Rs = 0.f;
    {
        float ppeP = ppeS, arp = arP, invp = invP, app = apP;
#pragma unroll
        for (int k = 0; k < 8; k++) {
            if (k < n) {
                float nrev = rev[k];
                float cogs = tr[k][1] * nrev;
                float opex = tr[k][2] * nrev;
                float dep  = tr[k][3] * ppeP;
                float intr = tr[k][9] * debt;
                float ebt  = nrev - cogs - opex - dep - intr;
                float tax  = tr[k][8] * fmaxf(ebt, 0.f);
                float ni   = ebt - tax;
                float arn  = tr[k][5] * nrev;
                float invn = tr[k][6] * cogs;
                float apn  = tr[k][7] * cogs;
                float capex = tr[k][4] * nrev;
                float cinc = ni + dep - capex - (arn - arp) - (invn - invp) + (apn - app);
                Cs += cinc; Rs += ni;
                ppeP = ppeP + capex - dep;
                arp = arn; invp = invn; app = apn;
            }
        }
    }
    float c = Cs;
#pragma unroll
    for (int dd = 1; dd < 32; dd <<= 1) {
        float v = __shfl_up_sync(FULL, c, dd);
        if (lane >= dd) c += v;
    }
    float ce = __shfl_up_sync(FULL, c, 1);
    if (lane == 0) ce = 0.f;
    float cashS = s0cash + ce;

    float rr = Rs;
#pragma unroll
    for (int dd = 1; dd < 32; dd <<= 1) {
        float v = __shfl_up_sync(FULL, rr, dd);
        if (lane >= dd) rr += v;
    }
    float re_e = __shfl_up_sync(FULL, rr, 1);
    if (lane == 0) re_e = 0.f;
    float reS = s0re + re_e;

    // ---- phase 4a: states walk -> skewed smem ----
    {
        float* sw = sbuf + w * STG_W;
        float cash = cashS, re = reS;
        float ppeP = ppeS, arp = arP, invp = invP, app = apP;
#pragma unroll
        for (int k = 0; k < 8; k++) {
            if (k < n) {
                float nrev = rev[k];
                float cogs = tr[k][1] * nrev;
                float opex = tr[k][2] * nrev;
                float dep  = tr[k][3] * ppeP;
                float intr = tr[k][9] * debt;
                float ebt  = nrev - cogs - opex - dep - intr;
                float tax  = tr[k][8] * fmaxf(ebt, 0.f);
                float ni   = ebt - tax;
                float arn  = tr[k][5] * nrev;
                float invn = tr[k][6] * cogs;
                float apn  = tr[k][7] * cogs;
                float capex = tr[k][4] * nrev;
                float ppen = ppeP + capex - dep;
                float cinc = ni + dep - capex - (arn - arp) - (invn - invp) + (apn - app);
                cash += cinc; re += ni;

                int idx = (o0 + k) * S_;
                sw[SKW(idx + 0)] = nrev;  sw[SKW(idx + 1)] = cash;
                sw[SKW(idx + 2)] = arn;   sw[SKW(idx + 3)] = invn;
                sw[SKW(idx + 4)] = ppen;  sw[SKW(idx + 5)] = apn;
                sw[SKW(idx + 6)] = debt;  sw[SKW(idx + 7)] = eqty;
                sw[SKW(idx + 8)] = re;    sw[SKW(idx + 9)] = oth;

                ppeP = ppen; arp = arn; invp = invn; app = apn;
            }
        }
    }
    __syncthreads();

    {
        int tid = threadIdx.x;
#pragma unroll
        for (int w2 = 0; w2 < 4; w2++) {
            const float* s = sbuf + w2 * STG_W;
            float* g = out + (long)(blockIdx.x * 4 + w2) * TO_ * S_;
            for (int i = tid; i < TO_ * S_; i += 128)
                g[i] = s[SKW(i)];
        }
    }
    __syncthreads();

    // ---- phase 4b: is walk -> skewed smem (reuse buffer) ----
    {
        float* sw = sbuf + w * ISG_W;
        float ppeP = ppeS, arp = arP, invp = invP, app = apP;
#pragma unroll
        for (int k = 0; k < 8; k++) {
            if (k < n) {
                float nrev = rev[k];
                float cogs = tr[k][1] * nrev;
                float opex = tr[k][2] * nrev;
                float dep  = tr[k][3] * ppeP;
                float intr = tr[k][9] * debt;
                float ebt  = nrev - cogs - opex - dep - intr;
                float tax  = tr[k][8] * fmaxf(ebt, 0.f);
                float ni   = ebt - tax;
                float capex = tr[k][4] * nrev;

                int idx = (o0 + k) * 7;
                sw[SKW(idx + 0)] = nrev;  sw[SKW(idx + 1)] = cogs;
                sw[SKW(idx + 2)] = opex;  sw[SKW(idx + 3)] = dep;
                sw[SKW(idx + 4)] = intr;  sw[SKW(idx + 5)] = tax;
                sw[SKW(idx + 6)] = ni;

                ppeP = ppeP + capex - dep;
                arp = tr[k][5] * nrev; invp = tr[k][6] * cogs; app = tr[k][7] * cogs;
            }
        }
    }
    __syncthreads();

    {
        int tid = threadIdx.x;
        float* ob = out + (long)B_ * TO_ * S_;
#pragma unroll
        for (int w2 = 0; w2 < 4; w2++) {
            const float* s = sbuf + w2 * ISG_W;
            float* g = ob + (long)(blockIdx.x * 4 + w2) * TO_ * 7;
            for (int i = tid; i < TO_ * 7; i += 128)
                g[i] = s[SKW(i)];
        }
    }
}

extern "C" void kernel_launch(void* const* d_in, const int* in_sizes, int n_in,
                              void* d_out, int out_size)
{
    const float* states = (const float*)d_in[0];
    const float* cov    = (const float*)d_in[1];
    const float* gamma  = (const float*)d_in[2];
    const float* beta   = (const float*)d_in[3];
    const float* wx     = (const float*)d_in[4];
    const float* wh     = (const float*)d_in[5];
    const float* rnn_b  = (const float*)d_in[6];
    const float* d1w    = (const float*)d_in[7];
    const float* d1b    = (const float*)d_in[8];
    const float* d2w    = (const float*)d_in[9];
    const float* d2b    = (const float*)d_in[10];
    float* out = (float*)d_out;

    k_ln_xw<<<(B_ * T_ / 2) / 256, 256>>>(cov, gamma, beta, wx, rnn_b);
    k_rnn<<<B_ / 8, 128>>>(wh);
    k_mlp<<<(B_ * T_) / 256, 256>>>(d1w, d1b, d2w, d2b);
    k_cash<<<B_ / 4, 128>>>(states, out);
}